// round 1
// baseline (speedup 1.0000x reference)
#include <cuda_runtime.h>
#include <cuda_bf16.h>
#include <math.h>

#define D_INNER 8192
#define D_MODEL 4096
#define DT_RANK 8
#define D_STATE 16
#define XP_DIM  (DT_RANK + 2 * D_STATE)   // 40

// Scratch (no allocations allowed in kernel_launch)
__device__ float g_x_conv[D_INNER];
__device__ float g_z_silu[D_INNER];
__device__ float g_xp[XP_DIM];
__device__ float g_y[D_INNER];

__device__ __forceinline__ float silu_f(float v) {
    return v / (1.0f + __expf(-v)) * 1.0f; // v * sigmoid(v)
}

// ---------------------------------------------------------------------------
// Kernel 1: xz = W_in @ x  (16384 x 4096), fused conv+silu epilogue.
// 8 warps/block, one row per warp, x staged in shared.
// ---------------------------------------------------------------------------
__global__ __launch_bounds__(256) void k_win(
    const float* __restrict__ W_in,
    const float* __restrict__ x,
    const float* __restrict__ conv_buffer,
    const float* __restrict__ conv_w,
    const float* __restrict__ conv_b)
{
    __shared__ float4 sx4[D_MODEL / 4];
    const int tid = threadIdx.x;
    const float4* x4 = (const float4*)x;
    #pragma unroll
    for (int i = tid; i < D_MODEL / 4; i += 256) sx4[i] = x4[i];
    __syncthreads();

    const int warp = tid >> 5;
    const int lane = tid & 31;
    const int row  = blockIdx.x * 8 + warp;

    const float4* w4 = (const float4*)(W_in + (size_t)row * D_MODEL);
    float acc = 0.0f;
    #pragma unroll 8
    for (int i = lane; i < D_MODEL / 4; i += 32) {
        float4 w = w4[i];
        float4 xv = sx4[i];
        acc = fmaf(w.x, xv.x, acc);
        acc = fmaf(w.y, xv.y, acc);
        acc = fmaf(w.z, xv.z, acc);
        acc = fmaf(w.w, xv.w, acc);
    }
    #pragma unroll
    for (int o = 16; o; o >>= 1) acc += __shfl_xor_sync(0xffffffffu, acc, o);

    if (lane == 0) {
        if (row < D_INNER) {
            // conv_in = [buf[:,1], buf[:,2], x_branch, x_branch] . conv_w + conv_b
            float v  = acc;
            float b1 = conv_buffer[row * 3 + 1];
            float b2 = conv_buffer[row * 3 + 2];
            float4 cw = ((const float4*)conv_w)[row];
            float s = fmaf(b1, cw.x, fmaf(b2, cw.y, fmaf(v, cw.z, fmaf(v, cw.w, conv_b[row]))));
            g_x_conv[row] = s / (1.0f + expf(-s));
        } else {
            float v = acc;
            g_z_silu[row - D_INNER] = v / (1.0f + expf(-v));
        }
    }
}

// ---------------------------------------------------------------------------
// Kernel 2: xp = W_xp @ x_conv  (40 x 8192). One block per row.
// ---------------------------------------------------------------------------
__global__ __launch_bounds__(256) void k_xp(const float* __restrict__ W_xp)
{
    __shared__ float red[8];
    const int row = blockIdx.x;
    const int tid = threadIdx.x;
    const float4* w4 = (const float4*)(W_xp + (size_t)row * D_INNER);
    const float4* v4 = (const float4*)g_x_conv;

    float acc = 0.0f;
    for (int i = tid; i < D_INNER / 4; i += 256) {
        float4 w = w4[i];
        float4 v = v4[i];
        acc = fmaf(w.x, v.x, acc);
        acc = fmaf(w.y, v.y, acc);
        acc = fmaf(w.z, v.z, acc);
        acc = fmaf(w.w, v.w, acc);
    }
    #pragma unroll
    for (int o = 16; o; o >>= 1) acc += __shfl_xor_sync(0xffffffffu, acc, o);
    const int warp = tid >> 5, lane = tid & 31;
    if (lane == 0) red[warp] = acc;
    __syncthreads();
    if (warp == 0) {
        float a = (lane < 8) ? red[lane] : 0.0f;
        #pragma unroll
        for (int o = 4; o; o >>= 1) a += __shfl_xor_sync(0xffffffffu, a, o);
        if (lane == 0) g_xp[row] = a;
    }
}

// ---------------------------------------------------------------------------
// Kernel 3: per-channel SSM update. 1 thread per channel.
// Writes new_h into d_out[4096:] and y -> g_y.
// ---------------------------------------------------------------------------
__global__ __launch_bounds__(256) void k_ssm(
    const float* __restrict__ W_dt,
    const float* __restrict__ b_dt,
    const float* __restrict__ ssm_state,
    const float* __restrict__ A_log,
    const float* __restrict__ D_param,
    float* __restrict__ d_out)
{
    __shared__ float sxp[XP_DIM];
    const int tid = threadIdx.x;
    if (tid < XP_DIM) sxp[tid] = g_xp[tid];
    __syncthreads();

    const int ch = blockIdx.x * 256 + tid;

    // dt = softplus(W_dt[ch,:] @ xp[:8] + b_dt[ch])
    float dtr = b_dt[ch];
    const float4* wd4 = (const float4*)(W_dt + (size_t)ch * DT_RANK);
    float4 w0 = wd4[0], w1 = wd4[1];
    dtr = fmaf(w0.x, sxp[0], dtr);
    dtr = fmaf(w0.y, sxp[1], dtr);
    dtr = fmaf(w0.z, sxp[2], dtr);
    dtr = fmaf(w0.w, sxp[3], dtr);
    dtr = fmaf(w1.x, sxp[4], dtr);
    dtr = fmaf(w1.y, sxp[5], dtr);
    dtr = fmaf(w1.z, sxp[6], dtr);
    dtr = fmaf(w1.w, sxp[7], dtr);
    float dt = (dtr > 20.0f) ? dtr : log1pf(expf(dtr));

    const float xc = g_x_conv[ch];
    const float* al = A_log + (size_t)ch * D_STATE;
    const float* st = ssm_state + (size_t)ch * D_STATE;
    float* hout = d_out + D_MODEL + (size_t)ch * D_STATE;

    float acc = 0.0f;
    #pragma unroll
    for (int s = 0; s < D_STATE; s++) {
        float A    = -expf(al[s]);
        float abar = expf(dt * A);
        float h    = fmaf(abar, st[s], dt * sxp[DT_RANK + s] * xc);
        hout[s] = h;
        acc = fmaf(h, sxp[DT_RANK + D_STATE + s], acc);
    }
    g_y[ch] = fmaf(D_param[ch], xc, acc) * g_z_silu[ch];
}

// ---------------------------------------------------------------------------
// Kernel 4: out = W_out @ y  (4096 x 8192). Warp per row, y in shared.
// ---------------------------------------------------------------------------
__global__ __launch_bounds__(256) void k_wout(
    const float* __restrict__ W_out,
    float* __restrict__ out)
{
    __shared__ float4 sy4[D_INNER / 4];
    const int tid = threadIdx.x;
    const float4* y4 = (const float4*)g_y;
    #pragma unroll
    for (int i = tid; i < D_INNER / 4; i += 256) sy4[i] = y4[i];
    __syncthreads();

    const int warp = tid >> 5;
    const int lane = tid & 31;
    const int row  = blockIdx.x * 8 + warp;

    const float4* w4 = (const float4*)(W_out + (size_t)row * D_INNER);
    float acc = 0.0f;
    #pragma unroll 8
    for (int i = lane; i < D_INNER / 4; i += 32) {
        float4 w = w4[i];
        float4 v = sy4[i];
        acc = fmaf(w.x, v.x, acc);
        acc = fmaf(w.y, v.y, acc);
        acc = fmaf(w.z, v.z, acc);
        acc = fmaf(w.w, v.w, acc);
    }
    #pragma unroll
    for (int o = 16; o; o >>= 1) acc += __shfl_xor_sync(0xffffffffu, acc, o);
    if (lane == 0) out[row] = acc;
}

// ---------------------------------------------------------------------------
extern "C" void kernel_launch(void* const* d_in, const int* in_sizes, int n_in,
                              void* d_out, int out_size)
{
    const float* x           = (const float*)d_in[0];
    const float* ssm_state   = (const float*)d_in[1];
    const float* conv_buffer = (const float*)d_in[2];
    const float* W_in        = (const float*)d_in[3];
    const float* conv_w      = (const float*)d_in[4];
    const float* conv_b      = (const float*)d_in[5];
    const float* W_xp        = (const float*)d_in[6];
    const float* W_dt        = (const float*)d_in[7];
    const float* b_dt        = (const float*)d_in[8];
    const float* A_log       = (const float*)d_in[9];
    const float* D_param     = (const float*)d_in[10];
    const float* W_out       = (const float*)d_in[11];
    float* out = (float*)d_out;

    k_win <<<(2 * D_INNER) / 8, 256>>>(W_in, x, conv_buffer, conv_w, conv_b);
    k_xp  <<<XP_DIM, 256>>>(W_xp);
    k_ssm <<<D_INNER / 256, 256>>>(W_dt, b_dt, ssm_state, A_log, D_param, out);
    k_wout<<<D_MODEL / 8, 256>>>(W_out, out);
}

// round 2
// speedup vs baseline: 1.0951x; 1.0951x over previous
#include <cuda_runtime.h>
#include <cuda_bf16.h>
#include <math.h>

#define D_INNER 8192
#define D_MODEL 4096
#define DT_RANK 8
#define D_STATE 16
#define XP_DIM  (DT_RANK + 2 * D_STATE)   // 40

#define KTILE   2048                      // split-K tile (floats)

// Scratch (no allocations allowed in kernel_launch)
__device__ float g_x_conv[D_INNER];
__device__ float g_z_silu[D_INNER];
__device__ float g_xp[XP_DIM];
__device__ float g_y[D_INNER];

// ---------------------------------------------------------------------------
// Kernel 1: xz = W_in @ x  (16384 x 4096), fused conv+silu epilogue.
// 8 warps/block, one row per warp, x staged in shared. grid=2048.
// Also zeroes g_xp for kernel 2's atomics (stream-ordered before k_xp).
// ---------------------------------------------------------------------------
__global__ __launch_bounds__(256) void k_win(
    const float* __restrict__ W_in,
    const float* __restrict__ x,
    const float* __restrict__ conv_buffer,
    const float* __restrict__ conv_w,
    const float* __restrict__ conv_b)
{
    __shared__ float4 sx4[D_MODEL / 4];
    const int tid = threadIdx.x;
    if (blockIdx.x == 0 && tid < XP_DIM) g_xp[tid] = 0.0f;

    const float4* x4 = (const float4*)x;
    #pragma unroll
    for (int i = tid; i < D_MODEL / 4; i += 256) sx4[i] = x4[i];
    __syncthreads();

    const int warp = tid >> 5;
    const int lane = tid & 31;
    const int row  = blockIdx.x * 8 + warp;

    const float4* w4 = (const float4*)(W_in + (size_t)row * D_MODEL);
    float acc = 0.0f;
    #pragma unroll 8
    for (int i = lane; i < D_MODEL / 4; i += 32) {
        float4 w = w4[i];
        float4 xv = sx4[i];
        acc = fmaf(w.x, xv.x, acc);
        acc = fmaf(w.y, xv.y, acc);
        acc = fmaf(w.z, xv.z, acc);
        acc = fmaf(w.w, xv.w, acc);
    }
    #pragma unroll
    for (int o = 16; o; o >>= 1) acc += __shfl_xor_sync(0xffffffffu, acc, o);

    if (lane == 0) {
        if (row < D_INNER) {
            float v  = acc;
            float b1 = conv_buffer[row * 3 + 1];
            float b2 = conv_buffer[row * 3 + 2];
            float4 cw = ((const float4*)conv_w)[row];
            float s = fmaf(b1, cw.x, fmaf(b2, cw.y, fmaf(v, cw.z, fmaf(v, cw.w, conv_b[row]))));
            g_x_conv[row] = s / (1.0f + expf(-s));
        } else {
            float v = acc;
            g_z_silu[row - D_INNER] = v / (1.0f + expf(-v));
        }
    }
}

// ---------------------------------------------------------------------------
// Kernel 2: xp = W_xp @ x_conv  (40 x 8192). Split-K: grid (40, 4),
// each block reduces a 2048-col chunk, atomicAdd into g_xp.
// ---------------------------------------------------------------------------
__global__ __launch_bounds__(256) void k_xp(const float* __restrict__ W_xp)
{
    __shared__ float red[8];
    const int row   = blockIdx.x;
    const int kbase = blockIdx.y * KTILE;
    const int tid   = threadIdx.x;

    const float4* w4 = (const float4*)(W_xp + (size_t)row * D_INNER + kbase);
    const float4* v4 = (const float4*)(g_x_conv + kbase);

    float acc = 0.0f;
    #pragma unroll
    for (int i = tid; i < KTILE / 4; i += 256) {
        float4 w = w4[i];
        float4 v = v4[i];
        acc = fmaf(w.x, v.x, acc);
        acc = fmaf(w.y, v.y, acc);
        acc = fmaf(w.z, v.z, acc);
        acc = fmaf(w.w, v.w, acc);
    }
    #pragma unroll
    for (int o = 16; o; o >>= 1) acc += __shfl_xor_sync(0xffffffffu, acc, o);
    const int warp = tid >> 5, lane = tid & 31;
    if (lane == 0) red[warp] = acc;
    __syncthreads();
    if (warp == 0) {
        float a = (lane < 8) ? red[lane] : 0.0f;
        #pragma unroll
        for (int o = 4; o; o >>= 1) a += __shfl_xor_sync(0xffffffffu, a, o);
        if (lane == 0) atomicAdd(&g_xp[row], a);
    }
}

// ---------------------------------------------------------------------------
// Kernel 3: per-channel SSM update. 1 thread per channel.
// Writes new_h into d_out[4096:], y -> g_y, and zeroes d_out[0:4096]
// for kernel 4's atomics (stream-ordered before k_wout).
// ---------------------------------------------------------------------------
__global__ __launch_bounds__(256) void k_ssm(
    const float* __restrict__ W_dt,
    const float* __restrict__ b_dt,
    const float* __restrict__ ssm_state,
    const float* __restrict__ A_log,
    const float* __restrict__ D_param,
    float* __restrict__ d_out)
{
    __shared__ float sxp[XP_DIM];
    const int tid = threadIdx.x;
    if (tid < XP_DIM) sxp[tid] = g_xp[tid];
    __syncthreads();

    const int ch = blockIdx.x * 256 + tid;
    if (ch < D_MODEL) d_out[ch] = 0.0f;

    float dtr = b_dt[ch];
    const float4* wd4 = (const float4*)(W_dt + (size_t)ch * DT_RANK);
    float4 w0 = wd4[0], w1 = wd4[1];
    dtr = fmaf(w0.x, sxp[0], dtr);
    dtr = fmaf(w0.y, sxp[1], dtr);
    dtr = fmaf(w0.z, sxp[2], dtr);
    dtr = fmaf(w0.w, sxp[3], dtr);
    dtr = fmaf(w1.x, sxp[4], dtr);
    dtr = fmaf(w1.y, sxp[5], dtr);
    dtr = fmaf(w1.z, sxp[6], dtr);
    dtr = fmaf(w1.w, sxp[7], dtr);
    float dt = (dtr > 20.0f) ? dtr : log1pf(expf(dtr));

    const float xc = g_x_conv[ch];
    const float* al = A_log + (size_t)ch * D_STATE;
    const float* st = ssm_state + (size_t)ch * D_STATE;
    float* hout = d_out + D_MODEL + (size_t)ch * D_STATE;

    float acc = 0.0f;
    #pragma unroll
    for (int s = 0; s < D_STATE; s++) {
        float A    = -expf(al[s]);
        float abar = expf(dt * A);
        float h    = fmaf(abar, st[s], dt * sxp[DT_RANK + s] * xc);
        hout[s] = h;
        acc = fmaf(h, sxp[DT_RANK + D_STATE + s], acc);
    }
    g_y[ch] = fmaf(D_param[ch], xc, acc) * g_z_silu[ch];
}

// ---------------------------------------------------------------------------
// Kernel 4: out = W_out @ y  (4096 x 8192). Split-K: grid (512, 4).
// Each block: 8 rows x 2048-col tile; 8KB y-slice in shared;
// warp partial -> atomicAdd into out (zeroed by k_ssm).
// ---------------------------------------------------------------------------
__global__ __launch_bounds__(256) void k_wout(
    const float* __restrict__ W_out,
    float* __restrict__ out)
{
    __shared__ float4 sy4[KTILE / 4];   // 8 KB
    const int tid   = threadIdx.x;
    const int kbase = blockIdx.y * KTILE;

    const float4* y4 = (const float4*)(g_y + kbase);
    #pragma unroll
    for (int i = tid; i < KTILE / 4; i += 256) sy4[i] = y4[i];
    __syncthreads();

    const int warp = tid >> 5;
    const int lane = tid & 31;
    const int row  = blockIdx.x * 8 + warp;

    const float4* w4 = (const float4*)(W_out + (size_t)row * D_INNER + kbase);
    float acc = 0.0f;
    #pragma unroll
    for (int i = lane; i < KTILE / 4; i += 32) {
        float4 w = w4[i];
        float4 v = sy4[i];
        acc = fmaf(w.x, v.x, acc);
        acc = fmaf(w.y, v.y, acc);
        acc = fmaf(w.z, v.z, acc);
        acc = fmaf(w.w, v.w, acc);
    }
    #pragma unroll
    for (int o = 16; o; o >>= 1) acc += __shfl_xor_sync(0xffffffffu, acc, o);
    if (lane == 0) atomicAdd(&out[row], acc);
}

// ---------------------------------------------------------------------------
extern "C" void kernel_launch(void* const* d_in, const int* in_sizes, int n_in,
                              void* d_out, int out_size)
{
    const float* x           = (const float*)d_in[0];
    const float* ssm_state   = (const float*)d_in[1];
    const float* conv_buffer = (const float*)d_in[2];
    const float* W_in        = (const float*)d_in[3];
    const float* conv_w      = (const float*)d_in[4];
    const float* conv_b      = (const float*)d_in[5];
    const float* W_xp        = (const float*)d_in[6];
    const float* W_dt        = (const float*)d_in[7];
    const float* b_dt        = (const float*)d_in[8];
    const float* A_log       = (const float*)d_in[9];
    const float* D_param     = (const float*)d_in[10];
    const float* W_out       = (const float*)d_in[11];
    float* out = (float*)d_out;

    k_win <<<(2 * D_INNER) / 8, 256>>>(W_in, x, conv_buffer, conv_w, conv_b);
    k_xp  <<<dim3(XP_DIM, D_INNER / KTILE), 256>>>(W_xp);
    k_ssm <<<D_INNER / 256, 256>>>(W_dt, b_dt, ssm_state, A_log, D_param, out);
    k_wout<<<dim3(D_MODEL / 8, D_INNER / KTILE), 256>>>(W_out, out);
}

// round 3
// speedup vs baseline: 1.1379x; 1.0391x over previous
#include <cuda_runtime.h>
#include <cuda_bf16.h>
#include <math.h>

#define D_INNER 8192
#define D_MODEL 4096
#define DT_RANK 8
#define D_STATE 16
#define XP_DIM  (DT_RANK + 2 * D_STATE)   // 40

#define KT_XP   1024                      // split-K tile for k_xp
#define KT_OUT  1024                      // split-K tile for k_wout

// Scratch (no allocations allowed in kernel_launch)
__device__ float g_x_conv[D_INNER];
__device__ float g_z_silu[D_INNER];
__device__ float g_xp[XP_DIM];
__device__ float g_y[D_INNER];

// ---------------------------------------------------------------------------
// Kernel 1: xz = W_in @ x  (16384 x 4096), fused conv+silu epilogue.
// 8 warps/block, one row per warp, x staged in shared. grid=2048.
// Zeroes g_xp for kernel 2's atomics.
// ---------------------------------------------------------------------------
__global__ __launch_bounds__(256) void k_win(
    const float* __restrict__ W_in,
    const float* __restrict__ x,
    const float* __restrict__ conv_buffer,
    const float* __restrict__ conv_w,
    const float* __restrict__ conv_b)
{
    __shared__ float4 sx4[D_MODEL / 4];
    const int tid = threadIdx.x;
    if (blockIdx.x == 0 && tid < XP_DIM) g_xp[tid] = 0.0f;

    const float4* x4 = (const float4*)x;
    #pragma unroll
    for (int i = tid; i < D_MODEL / 4; i += 256) sx4[i] = x4[i];
    __syncthreads();

    const int warp = tid >> 5;
    const int lane = tid & 31;
    const int row  = blockIdx.x * 8 + warp;

    const float4* w4 = (const float4*)(W_in + (size_t)row * D_MODEL);
    float acc0 = 0.0f, acc1 = 0.0f;
    #pragma unroll 8
    for (int i = lane; i < D_MODEL / 4; i += 64) {
        float4 w = __ldcs(&w4[i]);
        float4 xv = sx4[i];
        acc0 = fmaf(w.x, xv.x, acc0);
        acc0 = fmaf(w.y, xv.y, acc0);
        acc0 = fmaf(w.z, xv.z, acc0);
        acc0 = fmaf(w.w, xv.w, acc0);
        float4 w2 = __ldcs(&w4[i + 32]);
        float4 xv2 = sx4[i + 32];
        acc1 = fmaf(w2.x, xv2.x, acc1);
        acc1 = fmaf(w2.y, xv2.y, acc1);
        acc1 = fmaf(w2.z, xv2.z, acc1);
        acc1 = fmaf(w2.w, xv2.w, acc1);
    }
    float acc = acc0 + acc1;
    #pragma unroll
    for (int o = 16; o; o >>= 1) acc += __shfl_xor_sync(0xffffffffu, acc, o);

    if (lane == 0) {
        if (row < D_INNER) {
            float v  = acc;
            float b1 = conv_buffer[row * 3 + 1];
            float b2 = conv_buffer[row * 3 + 2];
            float4 cw = ((const float4*)conv_w)[row];
            float s = fmaf(b1, cw.x, fmaf(b2, cw.y, fmaf(v, cw.z, fmaf(v, cw.w, conv_b[row]))));
            g_x_conv[row] = s / (1.0f + expf(-s));
        } else {
            float v = acc;
            g_z_silu[row - D_INNER] = v / (1.0f + expf(-v));
        }
    }
}

// ---------------------------------------------------------------------------
// Kernel 2: xp = W_xp @ x_conv  (40 x 8192). Split-K grid (40, 8),
// atomicAdd into g_xp. Also zeroes d_out[0:4096] for k_wout's atomics.
// ---------------------------------------------------------------------------
__global__ __launch_bounds__(256) void k_xp(const float* __restrict__ W_xp,
                                            float* __restrict__ d_out)
{
    __shared__ float red[8];
    const int row   = blockIdx.x;
    const int kbase = blockIdx.y * KT_XP;
    const int tid   = threadIdx.x;

    // zero out[0:4096] using first 16 blocks of the (40,8) grid
    const int bflat = blockIdx.y * XP_DIM + blockIdx.x;
    if (bflat < D_MODEL / 256) d_out[bflat * 256 + tid] = 0.0f;

    const float4* w4 = (const float4*)(W_xp + (size_t)row * D_INNER + kbase);
    const float4* v4 = (const float4*)(g_x_conv + kbase);

    float acc = 0.0f;
    #pragma unroll
    for (int i = tid; i < KT_XP / 4; i += 256) {
        float4 w = __ldcs(&w4[i]);
        float4 v = v4[i];
        acc = fmaf(w.x, v.x, acc);
        acc = fmaf(w.y, v.y, acc);
        acc = fmaf(w.z, v.z, acc);
        acc = fmaf(w.w, v.w, acc);
    }
    #pragma unroll
    for (int o = 16; o; o >>= 1) acc += __shfl_xor_sync(0xffffffffu, acc, o);
    const int warp = tid >> 5, lane = tid & 31;
    if (lane == 0) red[warp] = acc;
    __syncthreads();
    if (warp == 0) {
        float a = (lane < 8) ? red[lane] : 0.0f;
        #pragma unroll
        for (int o = 4; o; o >>= 1) a += __shfl_xor_sync(0xffffffffu, a, o);
        if (lane == 0) atomicAdd(&g_xp[row], a);
    }
}

// ---------------------------------------------------------------------------
// Kernel 3: per-channel SSM update. 1 thread per channel.
// Writes new_h into d_out[4096:], y -> g_y.
// ---------------------------------------------------------------------------
__global__ __launch_bounds__(256) void k_ssm(
    const float* __restrict__ W_dt,
    const float* __restrict__ b_dt,
    const float* __restrict__ ssm_state,
    const float* __restrict__ A_log,
    const float* __restrict__ D_param,
    float* __restrict__ d_out)
{
    __shared__ float sxp[XP_DIM];
    const int tid = threadIdx.x;
    if (tid < XP_DIM) sxp[tid] = g_xp[tid];
    __syncthreads();

    const int ch = blockIdx.x * 256 + tid;

    float dtr = b_dt[ch];
    const float4* wd4 = (const float4*)(W_dt + (size_t)ch * DT_RANK);
    float4 w0 = wd4[0], w1 = wd4[1];
    dtr = fmaf(w0.x, sxp[0], dtr);
    dtr = fmaf(w0.y, sxp[1], dtr);
    dtr = fmaf(w0.z, sxp[2], dtr);
    dtr = fmaf(w0.w, sxp[3], dtr);
    dtr = fmaf(w1.x, sxp[4], dtr);
    dtr = fmaf(w1.y, sxp[5], dtr);
    dtr = fmaf(w1.z, sxp[6], dtr);
    dtr = fmaf(w1.w, sxp[7], dtr);
    float dt = (dtr > 20.0f) ? dtr : log1pf(expf(dtr));

    const float xc = g_x_conv[ch];
    const float* al = A_log + (size_t)ch * D_STATE;
    const float* st = ssm_state + (size_t)ch * D_STATE;
    float* hout = d_out + D_MODEL + (size_t)ch * D_STATE;

    float acc = 0.0f;
    #pragma unroll
    for (int s = 0; s < D_STATE; s++) {
        float A    = -expf(al[s]);
        float abar = expf(dt * A);
        float h    = fmaf(abar, st[s], dt * sxp[DT_RANK + s] * xc);
        hout[s] = h;
        acc = fmaf(h, sxp[DT_RANK + D_STATE + s], acc);
    }
    g_y[ch] = fmaf(D_param[ch], xc, acc) * g_z_silu[ch];
}

// ---------------------------------------------------------------------------
// Kernel 4: out = W_out @ y  (4096 x 8192). Split-K grid (512, 8).
// Each block: 8 rows x 1024-col tile; 4KB y-slice in shared;
// fully-unrolled 8x float4 per lane, 2 accumulators;
// warp partial -> atomicAdd into out (zeroed by k_xp).
// ---------------------------------------------------------------------------
__global__ __launch_bounds__(256) void k_wout(
    const float* __restrict__ W_out,
    float* __restrict__ out)
{
    __shared__ float4 sy4[KT_OUT / 4];   // 4 KB
    const int tid   = threadIdx.x;
    const int kbase = blockIdx.y * KT_OUT;

    const float4* y4 = (const float4*)(g_y + kbase);
    if (tid < KT_OUT / 4) sy4[tid] = y4[tid];
    __syncthreads();

    const int warp = tid >> 5;
    const int lane = tid & 31;
    const int row  = blockIdx.x * 8 + warp;

    const float4* w4 = (const float4*)(W_out + (size_t)row * D_INNER + kbase);
    float acc0 = 0.0f, acc1 = 0.0f;
    #pragma unroll
    for (int i = lane; i < KT_OUT / 4; i += 64) {
        float4 w = __ldcs(&w4[i]);
        float4 v = sy4[i];
        acc0 = fmaf(w.x, v.x, acc0);
        acc0 = fmaf(w.y, v.y, acc0);
        acc0 = fmaf(w.z, v.z, acc0);
        acc0 = fmaf(w.w, v.w, acc0);
        float4 w2 = __ldcs(&w4[i + 32]);
        float4 v2 = sy4[i + 32];
        acc1 = fmaf(w2.x, v2.x, acc1);
        acc1 = fmaf(w2.y, v2.y, acc1);
        acc1 = fmaf(w2.z, v2.z, acc1);
        acc1 = fmaf(w2.w, v2.w, acc1);
    }
    float acc = acc0 + acc1;
    #pragma unroll
    for (int o = 16; o; o >>= 1) acc += __shfl_xor_sync(0xffffffffu, acc, o);
    if (lane == 0) atomicAdd(&out[row], acc);
}

// ---------------------------------------------------------------------------
extern "C" void kernel_launch(void* const* d_in, const int* in_sizes, int n_in,
                              void* d_out, int out_size)
{
    const float* x           = (const float*)d_in[0];
    const float* ssm_state   = (const float*)d_in[1];
    const float* conv_buffer = (const float*)d_in[2];
    const float* W_in        = (const float*)d_in[3];
    const float* conv_w      = (const float*)d_in[4];
    const float* conv_b      = (const float*)d_in[5];
    const float* W_xp        = (const float*)d_in[6];
    const float* W_dt        = (const float*)d_in[7];
    const float* b_dt        = (const float*)d_in[8];
    const float* A_log       = (const float*)d_in[9];
    const float* D_param     = (const float*)d_in[10];
    const float* W_out       = (const float*)d_in[11];
    float* out = (float*)d_out;

    k_win <<<(2 * D_INNER) / 8, 256>>>(W_in, x, conv_buffer, conv_w, conv_b);
    k_xp  <<<dim3(XP_DIM, D_INNER / KT_XP), 256>>>(W_xp, out);
    k_ssm <<<D_INNER / 256, 256>>>(W_dt, b_dt, ssm_state, A_log, D_param, out);
    k_wout<<<dim3(D_MODEL / 8, D_INNER / KT_OUT), 256>>>(W_out, out);
}